// round 12
// baseline (speedup 1.0000x reference)
#include <cuda_runtime.h>
#include <cstdint>

// LIF layer scan: B=64, F=512, L=1024. rows = B*F = 32768.
// Output: z history then s history, each rows*L floats.
//
// Chunked scan: CH=4 chunks of 256 steps/row; chunks c>0 warm up over the
// preceding WUP=32 steps from v=0 (alpha^32 ~ 2e-5 decay; any spike resets
// v to exactly 0 -> exact resync). grid=4096.
//
// 4-stage cp.async pipeline, TT=16: 3 tile-groups (6KB) in flight per warp,
// smem 10.2KB/block -> 22 blocks/SM. Row stride 20 floats: 80B = 5*16
// (16B-aligned cp.async dsts), float4 LDS/STS conflict-free (phase bank
// starts {0,20,8,28,16,4,24,12} mod 32). z overwrites its input stage in
// place; s from z's sign bit; streaming (.cs) stores.
//
// R11 bug fixed: pipeline drain now waits by exact pending-group count
// (tile numTiles-2 previously used wait<2> with 2 groups pending -> raced).

#define L_DIM 1024
#define BR    32                 // rows per block = threads per block (1 warp)
#define TT    16                 // time-tile width
#define CH    4                  // chunks per row
#define CHL   (L_DIM / CH)       // 256 steps per chunk
#define WUP   32                 // warmup steps for chunks > 0
#define MT    (CHL / TT)         // 16 main tiles
#define WT    (WUP / TT)         // 2 warmup tiles
#define NSTG  4                  // pipeline stages
#define STRD  20                 // smem row stride (floats): 80B

__device__ __forceinline__ void cp_async16(uint32_t smem_dst, const void* gsrc) {
    asm volatile("cp.async.cg.shared.global [%0], [%1], 16;\n"
                 :: "r"(smem_dst), "l"(gsrc));
}
__device__ __forceinline__ void cp_commit() {
    asm volatile("cp.async.commit_group;\n");
}
template <int N>
__device__ __forceinline__ void cp_wait() {
    asm volatile("cp.async.wait_group %0;\n" :: "n"(N));
}

__device__ __forceinline__ float spike_of(float z) {
    // s = (z >= 0) ? 1.0f : 0.0f via sign bit (z == -0 cannot occur here)
    int zb = __float_as_int(z);
    return __int_as_float(0x3f800000 & ~(zb >> 31));
}

__global__ __launch_bounds__(BR) void lif_kernel(const float* __restrict__ I,
                                                 float* __restrict__ Z,
                                                 float* __restrict__ S) {
    __shared__ __align__(16) float sI[NSTG][BR][STRD];

    const int t        = threadIdx.x;
    const int chunk    = blockIdx.x & (CH - 1);
    const int rowBlk   = blockIdx.x >> 2;           // CH == 4
    const long rowBase = (long)rowBlk * BR;

    const int startT    = chunk * CHL - (chunk ? WUP : 0);
    const int numTiles  = chunk ? (WT + MT) : MT;
    const int storeFrom = chunk ? WT : 0;

    // alpha = float(exp(-DT/TAU)) = float(exp(-1/3))
    const float alpha = 0.71653131057378925043f;
    const float omal  = 1.0f - alpha;
    const float thr   = 0.25f;
    const float beta  = 10.0f;

    float v = 0.0f;

    const long chunkBase = rowBase * L_DIM + startT;

    // Per-thread tile slice: 4 x float4. e4 = k*BR + t ; r = e4/4 ;
    // c4 = (e4%4)*4 -> 4 consecutive threads fetch a row's 64B.

    // ---- prologue: issue tiles 0..2 ----
    #pragma unroll
    for (int p = 0; p < NSTG - 1; ++p) {
        const float* gb = I + chunkBase + p * TT;
        #pragma unroll
        for (int k = 0; k < 4; ++k) {
            int e4 = k * BR + t;
            int r  = e4 >> 2;
            int c4 = (e4 & 3) << 2;
            uint32_t dst = (uint32_t)__cvta_generic_to_shared(&sI[p][r][c4]);
            cp_async16(dst, gb + (long)r * L_DIM + c4);
        }
        cp_commit();
    }

    int cur = 0;   // stage index of current tile (tile % NSTG)

    #pragma unroll 1
    for (int tile = 0; tile < numTiles; ++tile) {
        const long gbase = chunkBase + (long)tile * TT;

        if (tile + NSTG - 1 < numTiles) {
            // ---- issue tile+3 into the stage vacated last iteration ----
            int nxt = cur + (NSTG - 1);
            if (nxt >= NSTG) nxt -= NSTG;
            const float* gb = I + gbase + (NSTG - 1) * TT;
            #pragma unroll
            for (int k = 0; k < 4; ++k) {
                int e4 = k * BR + t;
                int r  = e4 >> 2;
                int c4 = (e4 & 3) << 2;
                uint32_t dst = (uint32_t)__cvta_generic_to_shared(&sI[nxt][r][c4]);
                cp_async16(dst, gb + (long)r * L_DIM + c4);
            }
            cp_commit();
            cp_wait<NSTG - 1>();    // 3 groups pending after commit; wait<3>
                                    // ensures the oldest (current tile) landed
        } else {
            // ---- drain: wait by exact pending-group count ----
            const int pend = numTiles - tile;   // groups covering [tile, numTiles)
            if (pend >= 3)      { cp_wait<2>(); }
            else if (pend == 2) { cp_wait<1>(); }
            else                { cp_wait<0>(); }
        }
        __syncwarp();

        const bool doStore = (tile >= storeFrom);

        // ---- sequential scan of TT steps; z written back in place ----
        #pragma unroll
        for (int c = 0; c < TT; c += 4) {
            float4 i4 = *reinterpret_cast<const float4*>(&sI[cur][t][c]);
            float4 z4;
            float vp;
            vp = __fadd_rn(__fmul_rn(alpha, v), __fmul_rn(omal, i4.x));
            z4.x = __fmul_rn(beta, __fsub_rn(vp, thr));
            v = (vp >= thr) ? 0.0f : vp;
            vp = __fadd_rn(__fmul_rn(alpha, v), __fmul_rn(omal, i4.y));
            z4.y = __fmul_rn(beta, __fsub_rn(vp, thr));
            v = (vp >= thr) ? 0.0f : vp;
            vp = __fadd_rn(__fmul_rn(alpha, v), __fmul_rn(omal, i4.z));
            z4.z = __fmul_rn(beta, __fsub_rn(vp, thr));
            v = (vp >= thr) ? 0.0f : vp;
            vp = __fadd_rn(__fmul_rn(alpha, v), __fmul_rn(omal, i4.w));
            z4.w = __fmul_rn(beta, __fsub_rn(vp, thr));
            v = (vp >= thr) ? 0.0f : vp;
            if (doStore)
                *reinterpret_cast<float4*>(&sI[cur][t][c]) = z4;
        }

        if (doStore) {
            __syncwarp();
            // ---- coalesced streaming store of z and s (s from sign bit) ----
            #pragma unroll
            for (int k = 0; k < 4; ++k) {
                int e4 = k * BR + t;
                int r  = e4 >> 2;
                int c4 = (e4 & 3) << 2;
                float4 z4 = *reinterpret_cast<const float4*>(&sI[cur][r][c4]);
                float4 s4;
                s4.x = spike_of(z4.x);
                s4.y = spike_of(z4.y);
                s4.z = spike_of(z4.z);
                s4.w = spike_of(z4.w);
                long g = gbase + (long)r * L_DIM + c4;
                __stcs(reinterpret_cast<float4*>(&Z[g]), z4);
                __stcs(reinterpret_cast<float4*>(&S[g]), s4);
            }
        }
        __syncwarp();   // stage reads done before next iter's cp.async refills it

        ++cur;
        if (cur == NSTG) cur = 0;
    }
}

extern "C" void kernel_launch(void* const* d_in, const int* in_sizes, int n_in,
                              void* d_out, int out_size) {
    const float* I = (const float*)d_in[0];
    float* out = (float*)d_out;
    const int n    = in_sizes[0];        // B*F*L = 33554432
    const int rows = n / L_DIM;          // 32768
    float* Z = out;                      // z history first
    float* S = out + n;                  // then s history
    lif_kernel<<<(rows / BR) * CH, BR>>>(I, Z, S);
}

// round 14
// speedup vs baseline: 1.2055x; 1.2055x over previous
#include <cuda_runtime.h>
#include <cstdint>

// LIF layer scan: B=64, F=512, L=1024. rows = B*F = 32768.
// Output: z history then s history, each rows*L floats.
//
// R9 structure (best measured: 62.1us kernel, DRAM 72%):
//  - CH=4 chunks of 256 steps/row; chunks>0 warm up WUP=32 steps from v=0
//    (alpha^32 ~ 2e-5; spikes reset v to exactly 0 -> exact resync). grid=4096.
//  - 3-stage cp.async pipeline, TT=32: 2 tile-groups (8KB) in flight/warp.
//  - z overwrites its input stage in place (stage refilled only by the NEXT
//    iteration's cp.async, after this tile's store loop in program order).
//    smem 13.8KB/block -> 16 blocks/SM.
//  - Row stride 36 floats (144B = 9*16): 16B-aligned cp.async dsts,
//    conflict-free float4 LDS/STS. s from z's sign bit. .cs stores.
// This round: scan chain shortened with FFMA — vp = fmaf(alpha,v,omal*i),
// z = fmaf(beta,vp,-beta*thr). 6 -> 4 instr/step, chain ~25 -> ~12 cyc.

#define L_DIM 1024
#define BR    32                 // rows per block = threads per block (1 warp)
#define TT    32                 // time-tile width
#define CH    4                  // chunks per row
#define CHL   (L_DIM / CH)       // 256 steps per chunk
#define WUP   32                 // warmup steps for chunks > 0
#define MT    (CHL / TT)         // 8 main tiles
#define WT    (WUP / TT)         // 1 warmup tile
#define NSTG  3                  // pipeline stages
#define STRD  36                 // smem row stride (floats)

__device__ __forceinline__ void cp_async16(uint32_t smem_dst, const void* gsrc) {
    asm volatile("cp.async.cg.shared.global [%0], [%1], 16;\n"
                 :: "r"(smem_dst), "l"(gsrc));
}
__device__ __forceinline__ void cp_commit() {
    asm volatile("cp.async.commit_group;\n");
}
template <int N>
__device__ __forceinline__ void cp_wait() {
    asm volatile("cp.async.wait_group %0;\n" :: "n"(N));
}

__device__ __forceinline__ float spike_of(float z) {
    // s = (z >= 0) ? 1.0f : 0.0f via sign bit (z == -0 cannot occur here)
    int zb = __float_as_int(z);
    return __int_as_float(0x3f800000 & ~(zb >> 31));
}

__global__ __launch_bounds__(BR) void lif_kernel(const float* __restrict__ I,
                                                 float* __restrict__ Z,
                                                 float* __restrict__ S) {
    __shared__ __align__(16) float sI[NSTG][BR][STRD];

    const int t        = threadIdx.x;
    const int chunk    = blockIdx.x & (CH - 1);
    const int rowBlk   = blockIdx.x >> 2;           // CH == 4
    const long rowBase = (long)rowBlk * BR;

    const int startT    = chunk * CHL - (chunk ? WUP : 0);
    const int numTiles  = chunk ? (WT + MT) : MT;
    const int storeFrom = chunk ? WT : 0;

    // alpha = float(exp(-DT/TAU)) = float(exp(-1/3))
    const float alpha = 0.71653131057378925043f;
    const float omal  = 1.0f - alpha;
    const float thr   = 0.25f;
    const float beta  = 10.0f;
    const float nbt   = -beta * thr;     // -2.5f

    float v = 0.0f;

    const long chunkBase = rowBase * L_DIM + startT;

    // Per-thread tile slice: 8 x float4. e4 = k*BR + t ; r = e4/8 ;
    // c4 = (e4%8)*4 -> 8 consecutive threads fetch a row's 128B (full line).

    // ---- prologue: issue tiles 0 and 1 ----
    #pragma unroll
    for (int p = 0; p < NSTG - 1; ++p) {
        const float* gb = I + chunkBase + p * TT;
        #pragma unroll
        for (int k = 0; k < 8; ++k) {
            int e4 = k * BR + t;
            int r  = e4 >> 3;
            int c4 = (e4 & 7) << 2;
            uint32_t dst = (uint32_t)__cvta_generic_to_shared(&sI[p][r][c4]);
            cp_async16(dst, gb + (long)r * L_DIM + c4);
        }
        cp_commit();
    }

    int cur = 0;   // stage index of current tile (tile % NSTG)

    #pragma unroll 1
    for (int tile = 0; tile < numTiles; ++tile) {
        const long gbase = chunkBase + (long)tile * TT;

        if (tile + NSTG - 1 < numTiles) {
            // ---- issue tile+2 into the stage vacated last iteration ----
            int nxt = cur + (NSTG - 1);
            if (nxt >= NSTG) nxt -= NSTG;
            const float* gb = I + gbase + (NSTG - 1) * TT;
            #pragma unroll
            for (int k = 0; k < 8; ++k) {
                int e4 = k * BR + t;
                int r  = e4 >> 3;
                int c4 = (e4 & 7) << 2;
                uint32_t dst = (uint32_t)__cvta_generic_to_shared(&sI[nxt][r][c4]);
                cp_async16(dst, gb + (long)r * L_DIM + c4);
            }
            cp_commit();
            cp_wait<NSTG - 1>();    // <=2 pending => current tile landed
        } else {
            // ---- drain: wait by exact pending-group count ----
            const int pend = numTiles - tile;   // groups covering [tile, numTiles)
            if (pend >= 2) { cp_wait<1>(); }
            else           { cp_wait<0>(); }
        }
        __syncwarp();

        const bool doStore = (tile >= storeFrom);

        // ---- sequential scan of TT steps; z written back in place ----
        #pragma unroll
        for (int c = 0; c < TT; c += 4) {
            float4 i4 = *reinterpret_cast<const float4*>(&sI[cur][t][c]);
            float4 z4;
            float vp;
            vp = fmaf(alpha, v, __fmul_rn(omal, i4.x));
            z4.x = fmaf(beta, vp, nbt);
            v = (vp >= thr) ? 0.0f : vp;
            vp = fmaf(alpha, v, __fmul_rn(omal, i4.y));
            z4.y = fmaf(beta, vp, nbt);
            v = (vp >= thr) ? 0.0f : vp;
            vp = fmaf(alpha, v, __fmul_rn(omal, i4.z));
            z4.z = fmaf(beta, vp, nbt);
            v = (vp >= thr) ? 0.0f : vp;
            vp = fmaf(alpha, v, __fmul_rn(omal, i4.w));
            z4.w = fmaf(beta, vp, nbt);
            v = (vp >= thr) ? 0.0f : vp;
            if (doStore)
                *reinterpret_cast<float4*>(&sI[cur][t][c]) = z4;
        }

        if (doStore) {
            __syncwarp();
            // ---- coalesced streaming store of z and s (s from sign bit) ----
            #pragma unroll
            for (int k = 0; k < 8; ++k) {
                int e4 = k * BR + t;
                int r  = e4 >> 3;
                int c4 = (e4 & 7) << 2;
                float4 z4 = *reinterpret_cast<const float4*>(&sI[cur][r][c4]);
                float4 s4;
                s4.x = spike_of(z4.x);
                s4.y = spike_of(z4.y);
                s4.z = spike_of(z4.z);
                s4.w = spike_of(z4.w);
                long g = gbase + (long)r * L_DIM + c4;
                __stcs(reinterpret_cast<float4*>(&Z[g]), z4);
                __stcs(reinterpret_cast<float4*>(&S[g]), s4);
            }
        }
        __syncwarp();   // stage reads done before next iter's cp.async refills it

        ++cur;
        if (cur == NSTG) cur = 0;
    }
}

extern "C" void kernel_launch(void* const* d_in, const int* in_sizes, int n_in,
                              void* d_out, int out_size) {
    const float* I = (const float*)d_in[0];
    float* out = (float*)d_out;
    const int n    = in_sizes[0];        // B*F*L = 33554432
    const int rows = n / L_DIM;          // 32768
    float* Z = out;                      // z history first
    float* S = out + n;                  // then s history
    lif_kernel<<<(rows / BR) * CH, BR>>>(I, Z, S);
}